// round 6
// baseline (speedup 1.0000x reference)
#include <cuda_runtime.h>
#include <mma.h>
#include <cstdint>
#include <math.h>

using namespace nvcuda;

// Problem dims (SimpleLSTM): B=64, T=512, D=1024, H=1024
#define B_  64
#define T_  512
#define D_  1024
#define H_  1024
#define G4_ 4096   // 4*H

// ---------------- scratch (device globals: allocation-free) ----------------
__device__ float g_xproj[(size_t)T_ * B_ * G4_];   // [T*B][4H] fp32 (m = t*64+b)
// hidden state, A-frag permuted, f4 layout [ki(128)][strip(4)][lane(32)], v(4):
//   v0=h[strip*16 + ln/4][8ki + ln%4], v1=row+8, v2=col+4, v3=row+8,col+4
__device__ float g_hperm[2][B_ * H_];
__device__ unsigned int g_bar_count = 0;
__device__ unsigned int g_bar_gen = 0;

// ---------------- helpers ----------------
__device__ __forceinline__ void cp_async16(void* dst, const void* src) {
    uint32_t s = (uint32_t)__cvta_generic_to_shared(dst);
    asm volatile("cp.async.cg.shared.global [%0], [%1], 16;\n" :: "r"(s), "l"(src));
}
__device__ __forceinline__ void cp_commit() { asm volatile("cp.async.commit_group;\n"); }
template<int N>
__device__ __forceinline__ void cp_wait() { asm volatile("cp.async.wait_group %0;\n" :: "n"(N)); }

__device__ __forceinline__ float tf32_rnaf(float x) {
    unsigned r;
    asm("cvt.rna.tf32.f32 %0, %1;" : "=r"(r) : "f"(x));
    return __uint_as_float(r);
}
__device__ __forceinline__ void mma_tf32(float4& d, const uint4& a,
                                         unsigned b0, unsigned b1) {
    asm volatile(
        "mma.sync.aligned.m16n8k8.row.col.f32.tf32.tf32.f32 "
        "{%0,%1,%2,%3}, {%4,%5,%6,%7}, {%8,%9}, {%0,%1,%2,%3};"
        : "+f"(d.x), "+f"(d.y), "+f"(d.z), "+f"(d.w)
        : "r"(a.x), "r"(a.y), "r"(a.z), "r"(a.w), "r"(b0), "r"(b1));
}
__device__ __forceinline__ float sigmoid_f(float x) {
    return __fdividef(1.0f, 1.0f + __expf(-x));
}
__device__ __forceinline__ float tanh_f(float x) {
    return __fdividef(2.0f, 1.0f + __expf(-2.0f * x)) - 1.0f;
}

// ============================================================================
// Kernel A: xproj = xs @ Wx  (M=32768, N=4096, K=1024), tf32 wmma, cp.async
// (round-3 version, proven; ~1.6ms)
// ============================================================================
__global__ void __launch_bounds__(256) xproj_kernel(const float* __restrict__ xs,
                                                    const float* __restrict__ Wx) {
    constexpr int LDA = 36;
    constexpr int LDB = 132;
    extern __shared__ float smw[];
    float* As = smw;
    float* Bs = smw + 2 * 128 * LDA;

    const int tid = threadIdx.x;
    const int m0 = blockIdx.y * 128;
    const int n0 = blockIdx.x * 128;
    const int w  = tid >> 5;
    const int wm = w & 3;
    const int wn = w >> 2;

    wmma::fragment<wmma::accumulator, 16, 16, 8, float> acc[2][4];
    #pragma unroll
    for (int i = 0; i < 2; i++)
        #pragma unroll
        for (int j = 0; j < 4; j++)
            wmma::fill_fragment(acc[i][j], 0.0f);

    auto load_stage = [&](int st, int k0) {
        #pragma unroll
        for (int it = 0; it < 4; it++) {
            int idx = tid + it * 256;
            int row = idx >> 3;
            int q   = (idx & 7) * 4;
            int m   = m0 + row;
            int bb  = m & (B_ - 1);
            int tt  = m >> 6;
            cp_async16(&As[st * 128 * LDA + row * LDA + q],
                       xs + ((size_t)bb * T_ + tt) * D_ + k0 + q);
        }
        #pragma unroll
        for (int it = 0; it < 4; it++) {
            int idx = tid + it * 256;
            int row = idx >> 5;
            int q   = (idx & 31) * 4;
            cp_async16(&Bs[st * 32 * LDB + row * LDB + q],
                       Wx + (size_t)(k0 + row) * G4_ + n0 + q);
        }
    };

    load_stage(0, 0);
    cp_commit();

    for (int kc = 0; kc < 32; kc++) {
        if (kc + 1 < 32) load_stage((kc + 1) & 1, (kc + 1) * 32);
        cp_commit();
        cp_wait<1>();
        __syncthreads();

        const float* a_base = &As[(kc & 1) * 128 * LDA];
        const float* b_base = &Bs[(kc & 1) * 32 * LDB];
        #pragma unroll
        for (int kk = 0; kk < 32; kk += 8) {
            wmma::fragment<wmma::matrix_a, 16, 16, 8, wmma::precision::tf32, wmma::row_major> af[2];
            wmma::fragment<wmma::matrix_b, 16, 16, 8, wmma::precision::tf32, wmma::row_major> bf[4];
            #pragma unroll
            for (int mi = 0; mi < 2; mi++) {
                wmma::load_matrix_sync(af[mi], a_base + (wm * 32 + mi * 16) * LDA + kk, LDA);
                #pragma unroll
                for (int i = 0; i < af[mi].num_elements; i++)
                    af[mi].x[i] = wmma::__float_to_tf32(af[mi].x[i]);
            }
            #pragma unroll
            for (int nj = 0; nj < 4; nj++) {
                wmma::load_matrix_sync(bf[nj], b_base + kk * LDB + wn * 64 + nj * 16, LDB);
                #pragma unroll
                for (int i = 0; i < bf[nj].num_elements; i++)
                    bf[nj].x[i] = wmma::__float_to_tf32(bf[nj].x[i]);
            }
            #pragma unroll
            for (int mi = 0; mi < 2; mi++)
                #pragma unroll
                for (int nj = 0; nj < 4; nj++)
                    wmma::mma_sync(acc[mi][nj], af[mi], bf[nj], acc[mi][nj]);
        }
        __syncthreads();
    }

    #pragma unroll
    for (int mi = 0; mi < 2; mi++)
        #pragma unroll
        for (int nj = 0; nj < 4; nj++) {
            size_t row = (size_t)(m0 + wm * 32 + mi * 16);
            size_t col = (size_t)(n0 + wn * 64 + nj * 16);
            wmma::store_matrix_sync(g_xproj + row * G4_ + col, acc[mi][nj],
                                    G4_, wmma::mem_row_major);
        }
}

// ============================================================================
// Kernel B: persistent LSTM scan, 128 blocks x 256 threads (8 warps).
//   Block owns h-cols [bIdx*8,+8) x full batch. Warp (kq, nh): computes the
//   full 64-row tile for k-quarter kq, gate-col half nh (16 of 32 cols).
//   Per ki: 4 A-LDS.128 (shared w/ sibling nh warp) + 1 B-LDS.128 -> 8 MMAs.
//   Cross-warp reduce over 4 k-partials via DEDICATED sg (same as round 5).
//   2-stage cp.async pipeline. Round-3 atomic split arrive/wait barrier.
// ============================================================================
__global__ void __launch_bounds__(256, 1) lstm_scan_kernel(
    const float* __restrict__ c0, const float* __restrict__ h0,
    const float* __restrict__ Wh, const float* __restrict__ bias,
    float* __restrict__ out)
{
    extern __shared__ float sm[];
    // Whs: [kq(4)][ki2(32)][nh(2)][lane(32)][v(4)] = 32768 floats
    float*  Whs_f = sm;
    float4* Whs   = reinterpret_cast<float4*>(sm);
    // hs: 2 stages x 8192 floats (2048 f4)
    float*  hs_f  = sm + 32768;
    float4* hs    = reinterpret_cast<float4*>(hs_f);
    // sg: DEDICATED reduction staging [kq(4)][row(64) stride 34] = 8704 floats
    float*  sg    = sm + 32768 + 16384;

    const int tid  = threadIdx.x;
    const int lane = tid & 31;
    const int w    = tid >> 5;
    const int kq   = w & 3;             // k-quarter
    const int nh   = w >> 2;            // gate-col half (0: cols 0..15, 1: 16..31)
    const int bIdx = blockIdx.x;
    const int j0   = bIdx * 8;

    // ---- build Whs (tf32, B-frag permuted):
    //   k = (kq*32+ki2)*8 + (ln&3) + (v&1)*4 ; c = nh*16 + (ln>>2) + (v>>1)*8
    //   gate = c>>3, jc = c&7  ->  Wh[k][gate*H + j0 + jc]
    for (int i = tid; i < 32768; i += 256) {
        int v   = i & 3;
        int ln  = (i >> 2) & 31;
        int nhh = (i >> 7) & 1;
        int ki2 = (i >> 8) & 31;
        int kqq = i >> 13;
        int k = (kqq * 32 + ki2) * 8 + (ln & 3) + ((v & 1) << 2);
        int c = nhh * 16 + (ln >> 2) + ((v >> 1) << 3);
        int gate = c >> 3, jc = c & 7;
        Whs_f[i] = tf32_rnaf(__ldg(Wh + (size_t)k * G4_ + gate * H_ + j0 + jc));
    }

    // ---- per-thread ownership: 2 of the 512 (64 rows x 8 cols) cells
    //   e = tid + q*256 : row = e>>3 (0..63), col jj = e&7
    int br[2], jA[2];
    #pragma unroll
    for (int q = 0; q < 2; q++) {
        int e = tid + q * 256;
        br[q] = e >> 3;
        jA[q] = e & 7;
    }

    float creg[2], bia[2][4];
    #pragma unroll
    for (int q = 0; q < 2; q++) {
        int j = j0 + jA[q];
        #pragma unroll
        for (int g = 0; g < 4; g++) bia[q][g] = __ldg(bias + g * H_ + j);
        creg[q] = __ldg(c0 + (size_t)br[q] * H_ + j);
    }

    // ---- h-perm write coords (ki == bIdx): strip = row>>4, rr = row&15
    int strip_h[2], lane_h[2], v_h[2];
    #pragma unroll
    for (int q = 0; q < 2; q++) {
        int rr = br[q] & 15;
        strip_h[q] = br[q] >> 4;
        lane_h[q]  = (rr & 7) * 4 + (jA[q] & 3);
        v_h[q]     = ((rr >> 3) & 1) | ((jA[q] >> 2) << 1);
    }

    // ---- init g_hperm[0] = tf32(h0)
    #pragma unroll
    for (int q = 0; q < 2; q++) {
        size_t f4 = ((size_t)bIdx * 4 + strip_h[q]) * 32 + lane_h[q];
        g_hperm[0][f4 * 4 + v_h[q]] =
            tf32_rnaf(__ldg(h0 + (size_t)br[q] * H_ + j0 + jA[q]));
    }

    // ---- xproj prefetch
    float xpr[2][4];
    auto prefetch_xp = [&](int t) {
        const float* xp = g_xproj + (size_t)t * B_ * G4_;
        #pragma unroll
        for (int q = 0; q < 2; q++)
            #pragma unroll
            for (int g = 0; g < 4; g++)
                xpr[q][g] = __ldg(xp + (size_t)br[q] * G4_ + g * H_ + j0 + jA[q]);
    };
    prefetch_xp(0);

    // ---- initial grid sync (atomic, change-based: replay-safe)
    __syncthreads();
    if (tid == 0) {
        volatile unsigned int* genp = &g_bar_gen;
        unsigned int gen = *genp;
        __threadfence();
        unsigned int old = atomicAdd(&g_bar_count, 1u);
        if (old == 127u) {
            atomicExch(&g_bar_count, 0u);
            __threadfence();
            atomicAdd(&g_bar_gen, 1u);
        } else {
            while (*genp == gen) { }
            __threadfence();
        }
    }
    __syncthreads();

    for (int t = 0; t < T_; t++) {
        const float* hcur  = g_hperm[t & 1];
        float*       hnext = g_hperm[(t + 1) & 1];
        const float4* hc4  = reinterpret_cast<const float4*>(hcur);

        // stage = chunk ch: [kq(4)][dki(4)][strip(4)][lane(32)] f4 (2048 f4)
        auto issue = [&](int ch) {
            float4* dst = hs + (ch & 1) * 2048;
            #pragma unroll
            for (int it = 0; it < 8; it++) {
                int lin   = tid + it * 256;           // < 2048
                int ln    = lin & 31;
                int strip = (lin >> 5) & 3;
                int dki   = (lin >> 7) & 3;
                int kqq   = lin >> 9;
                cp_async16(&dst[lin],
                           &hc4[((size_t)(kqq * 32 + ch * 4 + dki) * 4 + strip) * 32 + ln]);
            }
        };

        issue(0); cp_commit();

        float4 acc[4][2];   // [strip][gate-group within nh half]
        #pragma unroll
        for (int s = 0; s < 4; s++)
            #pragma unroll
            for (int g = 0; g < 2; g++)
                acc[s][g] = make_float4(0.f, 0.f, 0.f, 0.f);

        #pragma unroll 1
        for (int ch = 0; ch < 8; ch++) {
            if (ch + 1 < 8) { issue(ch + 1); cp_commit(); }
            if (ch < 7) cp_wait<1>(); else cp_wait<0>();
            __syncthreads();

            const float4* st = hs + (ch & 1) * 2048;
            #pragma unroll
            for (int d = 0; d < 4; d++) {
                int ki2 = ch * 4 + d;
                uint4 a[4];
                #pragma unroll
                for (int s = 0; s < 4; s++)
                    a[s] = *reinterpret_cast<const uint4*>(
                        &st[((kq * 4 + d) * 4 + s) * 32 + lane]);
                uint4 b = *reinterpret_cast<const uint4*>(
                    &Whs[((kq * 32 + ki2) * 2 + nh) * 32 + lane]);
                #pragma unroll
                for (int s = 0; s < 4; s++) {
                    mma_tf32(acc[s][0], a[s], b.x, b.y);
                    mma_tf32(acc[s][1], a[s], b.z, b.w);
                }
            }
            __syncthreads();
        }

        // ---- stage partials: sg[kq][row (stride 34)][col = nh*16 + g*8 + c2]
        {
            int r  = lane >> 2;
            int c2 = (lane & 3) * 2;
            float* base = sg + (size_t)kq * 64 * 34;
            #pragma unroll
            for (int s = 0; s < 4; s++)
                #pragma unroll
                for (int g = 0; g < 2; g++) {
                    *reinterpret_cast<float2*>(
                        base + (s * 16 + r) * 34 + nh * 16 + g * 8 + c2) =
                        make_float2(acc[s][g].x, acc[s][g].y);
                    *reinterpret_cast<float2*>(
                        base + (s * 16 + r + 8) * 34 + nh * 16 + g * 8 + c2) =
                        make_float2(acc[s][g].z, acc[s][g].w);
                }
        }
        __syncthreads();

        // ---- reduce 4 k-quarters + fused elementwise (flax order i,f,g,o)
        float hnv[2];
        #pragma unroll
        for (int q = 0; q < 2; q++) {
            float gv[4];
            #pragma unroll
            for (int g = 0; g < 4; g++) {
                float sum = 0.f;
                #pragma unroll
                for (int kk = 0; kk < 4; kk++)
                    sum += sg[((size_t)kk * 64 + br[q]) * 34 + g * 8 + jA[q]];
                gv[g] = sum;
            }
            float pi = gv[0] + xpr[q][0] + bia[q][0];
            float pf = gv[1] + xpr[q][1] + bia[q][1];
            float pg = gv[2] + xpr[q][2] + bia[q][2];
            float po = gv[3] + xpr[q][3] + bia[q][3];
            float cn = sigmoid_f(pf) * creg[q] + sigmoid_f(pi) * tanh_f(pg);
            float hn = sigmoid_f(po) * tanh_f(cn);
            creg[q] = cn;
            hnv[q] = hn;
        }

        // ---- write hnext (tf32-rounded, permuted)
        #pragma unroll
        for (int q = 0; q < 2; q++) {
            size_t f4 = ((size_t)bIdx * 4 + strip_h[q]) * 32 + lane_h[q];
            hnext[f4 * 4 + v_h[q]] = tf32_rnaf(hnv[q]);
        }

        // ---- barrier arrive (round-3 atomic scheme)
        __syncthreads();
        unsigned int mygen = 0;
        if (tid == 0) {
            volatile unsigned int* genp = &g_bar_gen;
            mygen = *genp;
            __threadfence();                    // release h stores
            unsigned int old = atomicAdd(&g_bar_count, 1u);
            if (old == 127u) {
                atomicExch(&g_bar_count, 0u);
                __threadfence();
                atomicAdd(&g_bar_gen, 1u);
            }
        }

        // ---- hidden work between arrive and wait: ys stores + next prefetch
        #pragma unroll
        for (int q = 0; q < 2; q++)
            out[2 * B_ * H_ + ((size_t)br[q] * T_ + t) * H_ + j0 + jA[q]] = hnv[q];
        if (t == T_ - 1) {
            #pragma unroll
            for (int q = 0; q < 2; q++)
                out[B_ * H_ + (size_t)br[q] * H_ + j0 + jA[q]] = hnv[q];
        }
        if (t + 1 < T_) prefetch_xp(t + 1);

        // ---- barrier wait
        if (tid == 0) {
            volatile unsigned int* genp = &g_bar_gen;
            while (*genp == mygen) { }
            __threadfence();                    // acquire
        }
        __syncthreads();
    }

    // cT
    #pragma unroll
    for (int q = 0; q < 2; q++)
        out[(size_t)br[q] * H_ + j0 + jA[q]] = creg[q];
}

// ============================================================================
// Launch. Inputs: c0, h0, xs, Wx, Wh, b. Output fp32: [cT][hT][ys]
// ============================================================================
extern "C" void kernel_launch(void* const* d_in, const int* in_sizes, int n_in,
                              void* d_out, int out_size) {
    const float* c0   = (const float*)d_in[0];
    const float* h0   = (const float*)d_in[1];
    const float* xs   = (const float*)d_in[2];
    const float* Wx   = (const float*)d_in[3];
    const float* Wh   = (const float*)d_in[4];
    const float* bias = (const float*)d_in[5];
    float* out = (float*)d_out;

    constexpr int XPROJ_SMEM = (2 * 128 * 36 + 2 * 32 * 132) * 4;     // 70,656 B
    constexpr int SCAN_SMEM  = (32768 + 2 * 8192 + 8704) * 4;         // 231,424 B
    cudaFuncSetAttribute(xproj_kernel,
                         cudaFuncAttributeMaxDynamicSharedMemorySize, XPROJ_SMEM);
    cudaFuncSetAttribute(lstm_scan_kernel,
                         cudaFuncAttributeMaxDynamicSharedMemorySize, SCAN_SMEM);

    dim3 gridA(G4_ / 128, (T_ * B_) / 128);   // 32 x 256 blocks
    xproj_kernel<<<gridA, 256, XPROJ_SMEM>>>(xs, Wx);
    lstm_scan_kernel<<<128, 256, SCAN_SMEM>>>(c0, h0, Wh, bias, out);
}

// round 7
// speedup vs baseline: 1.0489x; 1.0489x over previous
#include <cuda_runtime.h>
#include <mma.h>
#include <cstdint>
#include <math.h>

using namespace nvcuda;

// Problem dims (SimpleLSTM): B=64, T=512, D=1024, H=1024
#define B_  64
#define T_  512
#define D_  1024
#define H_  1024
#define G4_ 4096   // 4*H

// ---------------- scratch (device globals: allocation-free) ----------------
__device__ float g_xproj[(size_t)T_ * B_ * G4_];   // [T*B][4H] fp32 (m = t*64+b)
// hidden state, A-frag permuted, f4 layout [ki(128)][strip(4)][lane(32)], v(4):
//   v0=h[strip*16 + ln/4][8ki + ln%4], v1=row+8, v2=col+4, v3=row+8,col+4
__device__ float g_hperm[2][B_ * H_];

// hierarchical barrier state (counters return to 0 after each use -> replay-safe)
struct PadCnt { unsigned v; unsigned pad[31]; };   // 128B spacing
__device__ PadCnt g_cnt1[8];
__device__ unsigned g_cnt2 = 0;
__device__ unsigned g_bar_gen = 0;

// ---------------- helpers ----------------
__device__ __forceinline__ void cp_async16(void* dst, const void* src) {
    uint32_t s = (uint32_t)__cvta_generic_to_shared(dst);
    asm volatile("cp.async.cg.shared.global [%0], [%1], 16;\n" :: "r"(s), "l"(src));
}
__device__ __forceinline__ void cp_commit() { asm volatile("cp.async.commit_group;\n"); }
template<int N>
__device__ __forceinline__ void cp_wait() { asm volatile("cp.async.wait_group %0;\n" :: "n"(N)); }

__device__ __forceinline__ float tf32_rnaf(float x) {
    unsigned r;
    asm("cvt.rna.tf32.f32 %0, %1;" : "=r"(r) : "f"(x));
    return __uint_as_float(r);
}
__device__ __forceinline__ void mma_tf32(float4& d, const uint4& a,
                                         unsigned b0, unsigned b1) {
    asm volatile(
        "mma.sync.aligned.m16n8k8.row.col.f32.tf32.tf32.f32 "
        "{%0,%1,%2,%3}, {%4,%5,%6,%7}, {%8,%9}, {%0,%1,%2,%3};"
        : "+f"(d.x), "+f"(d.y), "+f"(d.z), "+f"(d.w)
        : "r"(a.x), "r"(a.y), "r"(a.z), "r"(a.w), "r"(b0), "r"(b1));
}
__device__ __forceinline__ float sigmoid_f(float x) {
    return __fdividef(1.0f, 1.0f + __expf(-x));
}
__device__ __forceinline__ float tanh_f(float x) {
    return __fdividef(2.0f, 1.0f + __expf(-2.0f * x)) - 1.0f;
}

// hierarchical arrive: ~24 serialized atomic slots instead of 128.
__device__ __forceinline__ void bar_arrive(int bIdx) {
    __threadfence();                               // release prior global stores
    unsigned o = atomicAdd(&g_cnt1[bIdx >> 4].v, 1u);
    if (o == 15u) {
        unsigned o2 = atomicAdd(&g_cnt2, 1u);
        if (o2 == 7u) {
            #pragma unroll
            for (int i = 0; i < 8; i++) atomicExch(&g_cnt1[i].v, 0u);
            atomicExch(&g_cnt2, 0u);
            __threadfence();
            atomicAdd(&g_bar_gen, 1u);
        }
    }
}

// ============================================================================
// Kernel A: xproj = xs @ Wx  (M=32768, N=4096, K=1024), tf32 wmma, cp.async
// (round-3 version, proven; ~1.6ms)
// ============================================================================
__global__ void __launch_bounds__(256) xproj_kernel(const float* __restrict__ xs,
                                                    const float* __restrict__ Wx) {
    constexpr int LDA = 36;
    constexpr int LDB = 132;
    extern __shared__ float smw[];
    float* As = smw;
    float* Bs = smw + 2 * 128 * LDA;

    const int tid = threadIdx.x;
    const int m0 = blockIdx.y * 128;
    const int n0 = blockIdx.x * 128;
    const int w  = tid >> 5;
    const int wm = w & 3;
    const int wn = w >> 2;

    wmma::fragment<wmma::accumulator, 16, 16, 8, float> acc[2][4];
    #pragma unroll
    for (int i = 0; i < 2; i++)
        #pragma unroll
        for (int j = 0; j < 4; j++)
            wmma::fill_fragment(acc[i][j], 0.0f);

    auto load_stage = [&](int st, int k0) {
        #pragma unroll
        for (int it = 0; it < 4; it++) {
            int idx = tid + it * 256;
            int row = idx >> 3;
            int q   = (idx & 7) * 4;
            int m   = m0 + row;
            int bb  = m & (B_ - 1);
            int tt  = m >> 6;
            cp_async16(&As[st * 128 * LDA + row * LDA + q],
                       xs + ((size_t)bb * T_ + tt) * D_ + k0 + q);
        }
        #pragma unroll
        for (int it = 0; it < 4; it++) {
            int idx = tid + it * 256;
            int row = idx >> 5;
            int q   = (idx & 31) * 4;
            cp_async16(&Bs[st * 32 * LDB + row * LDB + q],
                       Wx + (size_t)(k0 + row) * G4_ + n0 + q);
        }
    };

    load_stage(0, 0);
    cp_commit();

    for (int kc = 0; kc < 32; kc++) {
        if (kc + 1 < 32) load_stage((kc + 1) & 1, (kc + 1) * 32);
        cp_commit();
        cp_wait<1>();
        __syncthreads();

        const float* a_base = &As[(kc & 1) * 128 * LDA];
        const float* b_base = &Bs[(kc & 1) * 32 * LDB];
        #pragma unroll
        for (int kk = 0; kk < 32; kk += 8) {
            wmma::fragment<wmma::matrix_a, 16, 16, 8, wmma::precision::tf32, wmma::row_major> af[2];
            wmma::fragment<wmma::matrix_b, 16, 16, 8, wmma::precision::tf32, wmma::row_major> bf[4];
            #pragma unroll
            for (int mi = 0; mi < 2; mi++) {
                wmma::load_matrix_sync(af[mi], a_base + (wm * 32 + mi * 16) * LDA + kk, LDA);
                #pragma unroll
                for (int i = 0; i < af[mi].num_elements; i++)
                    af[mi].x[i] = wmma::__float_to_tf32(af[mi].x[i]);
            }
            #pragma unroll
            for (int nj = 0; nj < 4; nj++) {
                wmma::load_matrix_sync(bf[nj], b_base + kk * LDB + wn * 64 + nj * 16, LDB);
                #pragma unroll
                for (int i = 0; i < bf[nj].num_elements; i++)
                    bf[nj].x[i] = wmma::__float_to_tf32(bf[nj].x[i]);
            }
            #pragma unroll
            for (int mi = 0; mi < 2; mi++)
                #pragma unroll
                for (int nj = 0; nj < 4; nj++)
                    wmma::mma_sync(acc[mi][nj], af[mi], bf[nj], acc[mi][nj]);
        }
        __syncthreads();
    }

    #pragma unroll
    for (int mi = 0; mi < 2; mi++)
        #pragma unroll
        for (int nj = 0; nj < 4; nj++) {
            size_t row = (size_t)(m0 + wm * 32 + mi * 16);
            size_t col = (size_t)(n0 + wn * 64 + nj * 16);
            wmma::store_matrix_sync(g_xproj + row * G4_ + col, acc[mi][nj],
                                    G4_, wmma::mem_row_major);
        }
}

// ============================================================================
// Kernel B: persistent LSTM scan, 128 blocks x 128 threads (4 warps).
//   Block owns h-cols [bIdx*8,+8) x full batch. Warp kq computes the FULL
//   64x32 gate tile over k-quarter kq. WARP-LOCAL cp.async pipeline:
//   16 chunks (ki2=2, 4KB/warp) x depth 4, each warp issues AND consumes its
//   own slice -> NO syncthreads in the GEMM loop. Cross-warp reduce via sg.
//   Hierarchical barrier arrive (8 group counters + master).
// ============================================================================
__global__ void __launch_bounds__(128, 1) lstm_scan_kernel(
    const float* __restrict__ c0, const float* __restrict__ h0,
    const float* __restrict__ Wh, const float* __restrict__ bias,
    float* __restrict__ out)
{
    extern __shared__ float sm[];
    // Whs: [kq(4)][ki2(32)][nh(2)][lane(32)][v(4)] = 32768 floats
    float*  Whs_f = sm;
    float4* Whs   = reinterpret_cast<float4*>(sm);
    // hs: warp-local stages [kq(4)][stage(4)][dki(2)][strip(4)][lane(32)] f4
    //     = 4096 f4 = 16384 floats
    float4* hs    = reinterpret_cast<float4*>(sm + 32768);
    // sg: reduction staging [kq(4)][row(64) stride 34] = 8704 floats
    float*  sg    = sm + 32768 + 16384;

    const int tid  = threadIdx.x;
    const int lane = tid & 31;
    const int kq   = tid >> 5;          // warp id == k-quarter
    const int bIdx = blockIdx.x;
    const int j0   = bIdx * 8;

    // ---- build Whs (tf32, B-frag permuted) — identical to round 5
    for (int i = tid; i < 32768; i += 128) {
        int v   = i & 3;
        int ln  = (i >> 2) & 31;
        int nh  = (i >> 7) & 1;
        int ki2 = (i >> 8) & 31;
        int kqq = i >> 13;
        int k = (kqq * 32 + ki2) * 8 + (ln & 3) + ((v & 1) << 2);
        int c = nh * 16 + (ln >> 2) + ((v >> 1) << 3);
        int gate = c >> 3, jc = c & 7;
        Whs_f[i] = tf32_rnaf(__ldg(Wh + (size_t)k * G4_ + gate * H_ + j0 + jc));
    }

    // ---- per-thread ownership: column j = j0 + (tid&7), rows b_q = rbase+16q
    const int rbase = tid >> 3;         // 0..15
    const int jj    = tid & 7;
    const int j     = j0 + jj;
    int bq[4];
    #pragma unroll
    for (int q = 0; q < 4; q++) bq[q] = rbase + q * 16;

    float creg[4], bia[4];
    #pragma unroll
    for (int g = 0; g < 4; g++) bia[g] = __ldg(bias + g * H_ + j);
    #pragma unroll
    for (int q = 0; q < 4; q++) creg[q] = __ldg(c0 + (size_t)bq[q] * H_ + j);

    // ---- h-perm write coords (fixed per thread; strip == q, ki == bIdx)
    const int lane_h = (rbase & 7) * 4 + (jj & 3);
    const int v_h    = ((rbase >> 3) & 1) | ((jj >> 2) << 1);

    // ---- init g_hperm[0] = tf32(h0)
    #pragma unroll
    for (int q = 0; q < 4; q++) {
        size_t f4 = ((size_t)bIdx * 4 + q) * 32 + lane_h;
        g_hperm[0][f4 * 4 + v_h] = tf32_rnaf(__ldg(h0 + (size_t)bq[q] * H_ + j));
    }

    // ---- xproj prefetch
    float xpr[4][4];
    auto prefetch_xp = [&](int t) {
        const float* xp = g_xproj + (size_t)t * B_ * G4_;
        #pragma unroll
        for (int q = 0; q < 4; q++)
            #pragma unroll
            for (int g = 0; g < 4; g++)
                xpr[q][g] = __ldg(xp + (size_t)bq[q] * G4_ + g * H_ + j);
    };
    prefetch_xp(0);

    // ---- initial grid sync
    __syncthreads();
    {
        unsigned mygen = 0;
        if (tid == 0) {
            volatile unsigned* genp = &g_bar_gen;
            mygen = *genp;
            bar_arrive(bIdx);
            while (*genp == mygen) { }
            __threadfence();
        }
        __syncthreads();
    }

    for (int t = 0; t < T_; t++) {
        const float* hcur  = g_hperm[t & 1];
        float*       hnext = g_hperm[(t + 1) & 1];
        const float4* hc4  = reinterpret_cast<const float4*>(hcur);

        // warp-local issue of chunk ch (ki2 = 2ch..2ch+1 of this warp's kq)
        auto issue = [&](int ch) {
            float4* dst = hs + kq * 1024 + (ch & 3) * 256;
            #pragma unroll
            for (int it = 0; it < 8; it++) {
                int dki   = it >> 2;
                int strip = it & 3;
                cp_async16(&dst[(dki * 4 + strip) * 32 + lane],
                           &hc4[((size_t)(kq * 32 + ch * 2 + dki) * 4 + strip) * 32 + lane]);
            }
        };

        issue(0); cp_commit();
        issue(1); cp_commit();
        issue(2); cp_commit();
        issue(3); cp_commit();

        float4 acc[4][4];   // [strip][gate-group]
        #pragma unroll
        for (int s = 0; s < 4; s++)
            #pragma unroll
            for (int g = 0; g < 4; g++)
                acc[s][g] = make_float4(0.f, 0.f, 0.f, 0.f);

        #pragma unroll 4
        for (int ch = 0; ch < 16; ch++) {
            if (ch < 13)      cp_wait<3>();
            else if (ch == 13) cp_wait<2>();
            else if (ch == 14) cp_wait<1>();
            else               cp_wait<0>();

            const float4* st = hs + kq * 1024 + (ch & 3) * 256;
            #pragma unroll
            for (int d = 0; d < 2; d++) {
                int ki2 = ch * 2 + d;
                uint4 a[4];
                #pragma unroll
                for (int s = 0; s < 4; s++)
                    a[s] = *reinterpret_cast<const uint4*>(&st[(d * 4 + s) * 32 + lane]);
                uint4 b0 = *reinterpret_cast<const uint4*>(
                    &Whs[((kq * 32 + ki2) * 2 + 0) * 32 + lane]);
                uint4 b1 = *reinterpret_cast<const uint4*>(
                    &Whs[((kq * 32 + ki2) * 2 + 1) * 32 + lane]);
                #pragma unroll
                for (int s = 0; s < 4; s++) {
                    mma_tf32(acc[s][0], a[s], b0.x, b0.y);
                    mma_tf32(acc[s][1], a[s], b0.z, b0.w);
                    mma_tf32(acc[s][2], a[s], b1.x, b1.y);
                    mma_tf32(acc[s][3], a[s], b1.z, b1.w);
                }
            }
            if (ch + 4 < 16) { issue(ch + 4); cp_commit(); }
        }

        // ---- stage partials: sg[kq][row (stride 34)][col = gate*8 + jj]
        {
            int r  = lane >> 2;
            int c2 = (lane & 3) * 2;
            float* base = sg + (size_t)kq * 64 * 34;
            #pragma unroll
            for (int s = 0; s < 4; s++)
                #pragma unroll
                for (int g = 0; g < 4; g++) {
                    *reinterpret_cast<float2*>(base + (s * 16 + r) * 34 + g * 8 + c2) =
                        make_float2(acc[s][g].x, acc[s][g].y);
                    *reinterpret_cast<float2*>(base + (s * 16 + r + 8) * 34 + g * 8 + c2) =
                        make_float2(acc[s][g].z, acc[s][g].w);
                }
        }
        __syncthreads();

        // ---- reduce 4 k-quarters + fused elementwise (flax order i,f,g,o)
        float hnv[4];
        #pragma unroll
        for (int q = 0; q < 4; q++) {
            float gv[4];
            #pragma unroll
            for (int g = 0; g < 4; g++) {
                float sum = 0.f;
                #pragma unroll
                for (int kk = 0; kk < 4; kk++)
                    sum += sg[((size_t)kk * 64 + bq[q]) * 34 + g * 8 + jj];
                gv[g] = sum;
            }
            float pi = gv[0] + xpr[q][0] + bia[0];
            float pf = gv[1] + xpr[q][1] + bia[1];
            float pg = gv[2] + xpr[q][2] + bia[2];
            float po = gv[3] + xpr[q][3] + bia[3];
            float cn = sigmoid_f(pf) * creg[q] + sigmoid_f(pi) * tanh_f(pg);
            float hn = sigmoid_f(po) * tanh_f(cn);
            creg[q] = cn;
            hnv[q] = hn;
        }

        // ---- write hnext (tf32-rounded, permuted)
        #pragma unroll
        for (int q = 0; q < 4; q++) {
            size_t f4 = ((size_t)bIdx * 4 + q) * 32 + lane_h;
            hnext[f4 * 4 + v_h] = tf32_rnaf(hnv[q]);
        }

        // ---- barrier arrive (hierarchical; releases h stores)
        __syncthreads();
        unsigned mygen = 0;
        if (tid == 0) {
            volatile unsigned* genp = &g_bar_gen;
            mygen = *genp;
            bar_arrive(bIdx);
        }

        // ---- hidden work between arrive and wait: ys stores + next prefetch
        #pragma unroll
        for (int q = 0; q < 4; q++)
            out[2 * B_ * H_ + ((size_t)bq[q] * T_ + t) * H_ + j] = hnv[q];
        if (t == T_ - 1) {
            #pragma unroll
            for (int q = 0; q < 4; q++)
                out[B_ * H_ + (size_t)bq[q] * H_ + j] = hnv[q];
        }
        if (t + 1 < T_) prefetch_xp(t + 1);

        // ---- barrier wait
        if (tid == 0) {
            volatile unsigned* genp = &g_bar_gen;
            while (*genp == mygen) { }
            __threadfence();                    // acquire
        }
        __syncthreads();
    }

    // cT
    #pragma unroll
    for (int q = 0; q < 4; q++)
        out[(size_t)bq[q] * H_ + j] = creg[q];
}

// ============================================================================
// Launch. Inputs: c0, h0, xs, Wx, Wh, b. Output fp32: [cT][hT][ys]
// ============================================================================
extern "C" void kernel_launch(void* const* d_in, const int* in_sizes, int n_in,
                              void* d_out, int out_size) {
    const float* c0   = (const float*)d_in[0];
    const float* h0   = (const float*)d_in[1];
    const float* xs   = (const float*)d_in[2];
    const float* Wx   = (const float*)d_in[3];
    const float* Wh   = (const float*)d_in[4];
    const float* bias = (const float*)d_in[5];
    float* out = (float*)d_out;

    constexpr int XPROJ_SMEM = (2 * 128 * 36 + 2 * 32 * 132) * 4;     // 70,656 B
    constexpr int SCAN_SMEM  = (32768 + 16384 + 8704) * 4;            // 231,424 B
    cudaFuncSetAttribute(xproj_kernel,
                         cudaFuncAttributeMaxDynamicSharedMemorySize, XPROJ_SMEM);
    cudaFuncSetAttribute(lstm_scan_kernel,
                         cudaFuncAttributeMaxDynamicSharedMemorySize, SCAN_SMEM);

    dim3 gridA(G4_ / 128, (T_ * B_) / 128);   // 32 x 256 blocks
    xproj_kernel<<<gridA, 256, XPROJ_SMEM>>>(xs, Wx);
    lstm_scan_kernel<<<128, 128, SCAN_SMEM>>>(c0, h0, Wh, bias, out);
}

// round 8
// speedup vs baseline: 1.5131x; 1.4426x over previous
#include <cuda_runtime.h>
#include <cstdint>
#include <math.h>

// Problem dims (SimpleLSTM): B=64, T=512, D=1024, H=1024
#define B_  64
#define T_  512
#define D_  1024
#define H_  1024
#define G4_ 4096   // 4*H

// ---------------- scratch (device globals: allocation-free) ----------------
__device__ float g_xproj[(size_t)T_ * B_ * G4_];      // [T*B][4H] fp32 (m = t*64+b)
__device__ float g_xsA[(size_t)2048 * 128 * 32 * 4];  // xs in A-frag layout (128MB)
__device__ float g_WxB[(size_t)128 * 128 * 2 * 32 * 4];// Wx in B-frag layout (16MB)
// hidden state, A-frag permuted, f4 layout [ki(128)][strip(4)][lane(32)], v(4):
//   v0=h[strip*16 + ln/4][8ki + ln%4], v1=row+8, v2=col+4, v3=row+8,col+4
__device__ float g_hperm[2][B_ * H_];

// hierarchical barrier state (counters return to 0 after each use -> replay-safe)
struct PadCnt { unsigned v; unsigned pad[31]; };   // 128B spacing
__device__ PadCnt g_cnt1[8];
__device__ unsigned g_cnt2 = 0;
__device__ unsigned g_bar_gen = 0;

// ---------------- helpers ----------------
__device__ __forceinline__ void cp_async16(void* dst, const void* src) {
    uint32_t s = (uint32_t)__cvta_generic_to_shared(dst);
    asm volatile("cp.async.cg.shared.global [%0], [%1], 16;\n" :: "r"(s), "l"(src));
}
__device__ __forceinline__ void cp_commit() { asm volatile("cp.async.commit_group;\n"); }
template<int N>
__device__ __forceinline__ void cp_wait() { asm volatile("cp.async.wait_group %0;\n" :: "n"(N)); }

__device__ __forceinline__ float tf32_rnaf(float x) {
    unsigned r;
    asm("cvt.rna.tf32.f32 %0, %1;" : "=r"(r) : "f"(x));
    return __uint_as_float(r);
}
__device__ __forceinline__ void mma_tf32(float4& d, const uint4& a,
                                         unsigned b0, unsigned b1) {
    asm volatile(
        "mma.sync.aligned.m16n8k8.row.col.f32.tf32.tf32.f32 "
        "{%0,%1,%2,%3}, {%4,%5,%6,%7}, {%8,%9}, {%0,%1,%2,%3};"
        : "+f"(d.x), "+f"(d.y), "+f"(d.z), "+f"(d.w)
        : "r"(a.x), "r"(a.y), "r"(a.z), "r"(a.w), "r"(b0), "r"(b1));
}
__device__ __forceinline__ float sigmoid_f(float x) {
    return __fdividef(1.0f, 1.0f + __expf(-x));
}
__device__ __forceinline__ float tanh_f(float x) {
    return __fdividef(2.0f, 1.0f + __expf(-2.0f * x)) - 1.0f;
}

// hierarchical arrive: ~24 serialized atomic slots instead of 128.
__device__ __forceinline__ void bar_arrive(int bIdx) {
    __threadfence();                               // release prior global stores
    unsigned o = atomicAdd(&g_cnt1[bIdx >> 4].v, 1u);
    if (o == 15u) {
        unsigned o2 = atomicAdd(&g_cnt2, 1u);
        if (o2 == 7u) {
            #pragma unroll
            for (int i = 0; i < 8; i++) atomicExch(&g_cnt1[i].v, 0u);
            atomicExch(&g_cnt2, 0u);
            __threadfence();
            atomicAdd(&g_bar_gen, 1u);
        }
    }
}

// ============================================================================
// P1: permute xs -> g_xsA (A-frag layout, tf32-rounded).
//   f4 index x: lane=x&31, ki=(x>>5)&127, strip=x>>12. m maps time-major:
//   m = t*64 + b  ->  b = m&63, t = m>>6.
// ============================================================================
__global__ void __launch_bounds__(256) permA_kernel(const float* __restrict__ xs) {
    size_t x = (size_t)blockIdx.x * 256 + threadIdx.x;   // < 2048*128*32
    int lane  = (int)(x & 31);
    int ki    = (int)((x >> 5) & 127);
    int strip = (int)(x >> 12);
    int r  = strip * 16 + (lane >> 2);
    int k  = ki * 8 + (lane & 3);
    auto src = [&](int m, int kk) -> float {
        int b = m & 63, t = m >> 6;
        return xs[((size_t)b * T_ + t) * D_ + kk];
    };
    float4 v;
    v.x = tf32_rnaf(src(r,     k));
    v.y = tf32_rnaf(src(r + 8, k));
    v.z = tf32_rnaf(src(r,     k + 4));
    v.w = tf32_rnaf(src(r + 8, k + 4));
    *reinterpret_cast<float4*>(g_xsA + x * 4) = v;
}

// ============================================================================
// P2: permute Wx -> g_WxB (B-frag layout, tf32-rounded).
//   f4 index y: lane=y&31, nh=(y>>5)&1, ki=(y>>6)&127, ng=y>>13.
//   col c = ng*32 + nh*16 + (lane>>2); v = {B[k][c],B[k+4][c],B[k][c+8],B[k+4][c+8]}
// ============================================================================
__global__ void __launch_bounds__(256) permB_kernel(const float* __restrict__ Wx) {
    size_t y = (size_t)blockIdx.x * 256 + threadIdx.x;   // < 128*128*2*32
    int lane = (int)(y & 31);
    int nh   = (int)((y >> 5) & 1);
    int ki   = (int)((y >> 6) & 127);
    int ng   = (int)(y >> 13);
    int c = ng * 32 + nh * 16 + (lane >> 2);
    int k = ki * 8 + (lane & 3);
    float4 v;
    v.x = tf32_rnaf(Wx[(size_t)k * G4_ + c]);
    v.y = tf32_rnaf(Wx[(size_t)(k + 4) * G4_ + c]);
    v.z = tf32_rnaf(Wx[(size_t)k * G4_ + c + 8]);
    v.w = tf32_rnaf(Wx[(size_t)(k + 4) * G4_ + c + 8]);
    *reinterpret_cast<float4*>(g_WxB + y * 4) = v;
}

// ============================================================================
// Kernel G: xproj = xsA @ WxB  (M=32768, N=4096, K=1024), mma.sync tf32.
// 256 thr, 8 warps (wm 0..1 x wn 0..3), warp tile m64 x n32.
// Block tile 128x128, 16 k-chunks of 8 ki, 3-stage cp.async (2-deep coverage).
// ============================================================================
__global__ void __launch_bounds__(256) xproj_kernel() {
    extern __shared__ float4 smG[];   // 3 stages x (A 2048 + B 2048) f4
    const int tid  = threadIdx.x;
    const int lane = tid & 31;
    const int w    = tid >> 5;
    const int wm   = w >> 2;    // 0..1
    const int wn   = w & 3;     // 0..3
    const int mt   = blockIdx.y;       // 0..255
    const int nt   = blockIdx.x;       // 0..31

    const float4* xsA = reinterpret_cast<const float4*>(g_xsA);
    const float4* WxB = reinterpret_cast<const float4*>(g_WxB);

    auto issue = [&](int ch) {
        float4* stA = smG + (ch % 3) * 4096;
        float4* stB = stA + 2048;
        #pragma unroll
        for (int it = 0; it < 8; it++) {
            int lin = tid + it * 256;                  // 2048
            int ln  = lin & 31;
            int dki = (lin >> 5) & 7;
            int st  = lin >> 8;
            cp_async16(&stA[lin],
                       &xsA[((size_t)(mt * 8 + st) * 128 + ch * 8 + dki) * 32 + ln]);
        }
        #pragma unroll
        for (int it = 0; it < 8; it++) {
            int lin = tid + it * 256;
            int ln  = lin & 31;
            int nh  = (lin >> 5) & 1;
            int dki = (lin >> 6) & 7;
            int ng  = lin >> 9;
            cp_async16(&stB[lin],
                       &WxB[(((size_t)(nt * 4 + ng) * 128 + ch * 8 + dki) * 2 + nh) * 32 + ln]);
        }
    };

    float4 acc[4][4];
    #pragma unroll
    for (int s = 0; s < 4; s++)
        #pragma unroll
        for (int g = 0; g < 4; g++)
            acc[s][g] = make_float4(0.f, 0.f, 0.f, 0.f);

    issue(0); cp_commit();
    issue(1); cp_commit();

    #pragma unroll 1
    for (int ch = 0; ch < 16; ch++) {
        __syncthreads();                       // readers of stage (ch+2)%3 done
        if (ch + 2 < 16) { issue(ch + 2); cp_commit(); }
        if (ch < 14) cp_wait<2>(); else if (ch == 14) cp_wait<1>(); else cp_wait<0>();
        __syncthreads();

        const float4* stA = smG + (ch % 3) * 4096;
        const float4* stB = stA + 2048;
        #pragma unroll
        for (int d = 0; d < 8; d++) {
            uint4 a[4];
            #pragma unroll
            for (int s = 0; s < 4; s++)
                a[s] = *reinterpret_cast<const uint4*>(
                    &stA[((wm * 4 + s) * 8 + d) * 32 + lane]);
            uint4 b0 = *reinterpret_cast<const uint4*>(&stB[((wn * 8 + d) * 2 + 0) * 32 + lane]);
            uint4 b1 = *reinterpret_cast<const uint4*>(&stB[((wn * 8 + d) * 2 + 1) * 32 + lane]);
            #pragma unroll
            for (int s = 0; s < 4; s++) {
                mma_tf32(acc[s][0], a[s], b0.x, b0.y);
                mma_tf32(acc[s][1], a[s], b0.z, b0.w);
                mma_tf32(acc[s][2], a[s], b1.x, b1.y);
                mma_tf32(acc[s][3], a[s], b1.z, b1.w);
            }
        }
    }

    // epilogue: fp32 rows to g_xproj
    int r  = lane >> 2;
    int c2 = (lane & 3) * 2;
    #pragma unroll
    for (int s = 0; s < 4; s++)
        #pragma unroll
        for (int g = 0; g < 4; g++) {
            size_t row = (size_t)mt * 128 + (wm * 4 + s) * 16 + r;
            size_t col = (size_t)nt * 128 + wn * 32 + g * 8 + c2;
            *reinterpret_cast<float2*>(g_xproj + row * G4_ + col) =
                make_float2(acc[s][g].x, acc[s][g].y);
            *reinterpret_cast<float2*>(g_xproj + (row + 8) * G4_ + col) =
                make_float2(acc[s][g].z, acc[s][g].w);
        }
}

// ============================================================================
// Kernel B: persistent LSTM scan (round-7 version, PASSING, byte-identical).
// 128 blocks x 128 threads (4 warps). Warp-local cp.async pipeline, no
// syncthreads in GEMM loop, hierarchical atomic barrier.
// ============================================================================
__global__ void __launch_bounds__(128, 1) lstm_scan_kernel(
    const float* __restrict__ c0, const float* __restrict__ h0,
    const float* __restrict__ Wh, const float* __restrict__ bias,
    float* __restrict__ out)
{
    extern __shared__ float sm[];
    // Whs: [kq(4)][ki2(32)][nh(2)][lane(32)][v(4)] = 32768 floats
    float*  Whs_f = sm;
    float4* Whs   = reinterpret_cast<float4*>(sm);
    // hs: warp-local stages [kq(4)][stage(4)][dki(2)][strip(4)][lane(32)] f4
    float4* hs    = reinterpret_cast<float4*>(sm + 32768);
    // sg: reduction staging [kq(4)][row(64) stride 34] = 8704 floats
    float*  sg    = sm + 32768 + 16384;

    const int tid  = threadIdx.x;
    const int lane = tid & 31;
    const int kq   = tid >> 5;          // warp id == k-quarter
    const int bIdx = blockIdx.x;
    const int j0   = bIdx * 8;

    // ---- build Whs (tf32, B-frag permuted)
    for (int i = tid; i < 32768; i += 128) {
        int v   = i & 3;
        int ln  = (i >> 2) & 31;
        int nh  = (i >> 7) & 1;
        int ki2 = (i >> 8) & 31;
        int kqq = i >> 13;
        int k = (kqq * 32 + ki2) * 8 + (ln & 3) + ((v & 1) << 2);
        int c = nh * 16 + (ln >> 2) + ((v >> 1) << 3);
        int gate = c >> 3, jc = c & 7;
        Whs_f[i] = tf32_rnaf(__ldg(Wh + (size_t)k * G4_ + gate * H_ + j0 + jc));
    }

    // ---- per-thread ownership: column j = j0 + (tid&7), rows b_q = rbase+16q
    const int rbase = tid >> 3;         // 0..15
    const int jj    = tid & 7;
    const int j     = j0 + jj;
    int bq[4];
    #pragma unroll
    for (int q = 0; q < 4; q++) bq[q] = rbase + q * 16;

    float creg[4], bia[4];
    #pragma unroll
    for (int g = 0; g < 4; g++) bia[g] = __ldg(bias + g * H_ + j);
    #pragma unroll
    for (int q = 0; q < 4; q++) creg[q] = __ldg(c0 + (size_t)bq[q] * H_ + j);

    // ---- h-perm write coords (fixed per thread; strip == q, ki == bIdx)
    const int lane_h = (rbase & 7) * 4 + (jj & 3);
    const int v_h    = ((rbase >> 3) & 1) | ((jj >> 2) << 1);

    // ---- init g_hperm[0] = tf32(h0)
    #pragma unroll
    for (int q = 0; q < 4; q++) {
        size_t f4 = ((size_t)bIdx * 4 + q) * 32 + lane_h;
        g_hperm[0][f4 * 4 + v_h] = tf32_rnaf(__ldg(h0 + (size_t)bq[q] * H_ + j));
    }

    // ---- xproj prefetch
    float xpr[4][4];
    auto prefetch_xp = [&](int t) {
        const float* xp = g_xproj + (size_t)t * B_ * G4_;
        #pragma unroll
        for (int q = 0; q < 4; q++)
            #pragma unroll
            for (int g = 0; g < 4; g++)
                xpr[q][g] = __ldg(xp + (size_t)bq[q] * G4_ + g * H_ + j);
    };
    prefetch_xp(0);

    // ---- initial grid sync
    __syncthreads();
    {
        unsigned mygen = 0;
        if (tid == 0) {
            volatile unsigned* genp = &g_bar_gen;
            mygen = *genp;
            bar_arrive(bIdx);
            while (*genp == mygen) { }
            __threadfence();
        }
        __syncthreads();
    }

    for (int t = 0; t < T_; t++) {
        const float* hcur  = g_hperm[t & 1];
        float*       hnext = g_hperm[(t + 1) & 1];
        const float4* hc4  = reinterpret_cast<const float4*>(hcur);

        // warp-local issue of chunk ch (ki2 = 2ch..2ch+1 of this warp's kq)
        auto issue = [&](int ch) {
            float4* dst = hs + kq * 1024 + (ch & 3) * 256;
            #pragma unroll
            for (int it = 0; it < 8; it++) {
                int dki   = it >> 2;
                int strip = it & 3;
                cp_async16(&dst[(dki * 4 + strip) * 32 + lane],
                           &hc4[((size_t)(kq * 32 + ch * 2 + dki) * 4 + strip) * 32 + lane]);
            }
        };

        issue(0); cp_commit();
        issue(1); cp_commit();
        issue(2); cp_commit();
        issue(3); cp_commit();

        float4 acc[4][4];   // [strip][gate-group]
        #pragma unroll
        for (int s = 0; s < 4; s++)
            #pragma unroll
            for (int g = 0; g < 4; g++)
                acc[s][g] = make_float4(0.f, 0.f, 0.f, 0.f);

        #pragma unroll 4
        for (int ch = 0; ch < 16; ch++) {
            if (ch < 13)      cp_wait<3>();
            else if (ch == 13) cp_wait<2>();
            else if (ch == 14) cp_wait<1>();
            else               cp_wait<0>();

            const float4* st = hs + kq * 1024 + (ch & 3) * 256;
            #pragma unroll
            for (int d = 0; d < 2; d++) {
                int ki2 = ch * 2 + d;
                uint4 a[4];
                #pragma unroll
                for (int s = 0; s < 4; s++)
                    a[s] = *reinterpret_cast<const uint4*>(&st[(d * 4 + s) * 32 + lane]);
                uint4 b0 = *reinterpret_cast<const uint4*>(
                    &Whs[((kq * 32 + ki2) * 2 + 0) * 32 + lane]);
                uint4 b1 = *reinterpret_cast<const uint4*>(
                    &Whs[((kq * 32 + ki2) * 2 + 1) * 32 + lane]);
                #pragma unroll
                for (int s = 0; s < 4; s++) {
                    mma_tf32(acc[s][0], a[s], b0.x, b0.y);
                    mma_tf32(acc[s][1], a[s], b0.z, b0.w);
                    mma_tf32(acc[s][2], a[s], b1.x, b1.y);
                    mma_tf32(acc[s][3], a[s], b1.z, b1.w);
                }
            }
            if (ch + 4 < 16) { issue(ch + 4); cp_commit(); }
        }

        // ---- stage partials: sg[kq][row (stride 34)][col = gate*8 + jj]
        {
            int r  = lane >> 2;
            int c2 = (lane & 3) * 2;
            float* base = sg + (size_t)kq * 64 * 34;
            #pragma unroll
            for (int s = 0; s < 4; s++)
                #pragma unroll
                for (int g = 0; g < 4; g++) {
                    *reinterpret_cast<float2*>(base + (s * 16 + r) * 34 + g * 8 + c2) =
                        make_float2(acc[s][g].x, acc[s][g].y);
                    *reinterpret_cast<float2*>(base + (s * 16 + r + 8) * 34 + g * 8 + c2) =
                        make_float2(acc[s][g].z, acc[s][g].w);
                }
        }
        __syncthreads();

        // ---- reduce 4 k-quarters + fused elementwise (flax order i,f,g,o)
        float hnv[4];
        #pragma unroll
        for (int q = 0; q < 4; q++) {
            float gv[4];
            #pragma unroll
            for (int g = 0; g < 4; g++) {
                float sum = 0.f;
                #pragma unroll
                for (int kk = 0; kk < 4; kk++)
                    sum += sg[((size_t)kk * 64 + bq[q]) * 34 + g * 8 + jj];
                gv[g] = sum;
            }
            float pi = gv[0] + xpr[q][0] + bia[0];
            float pf = gv[1] + xpr[q][1] + bia[1];
            float pg = gv[2] + xpr[q][2] + bia[2];
            float po = gv[3] + xpr[q][3] + bia[3];
            float cn = sigmoid_f(pf) * creg[q] + sigmoid_f(pi) * tanh_f(pg);
            float hn = sigmoid_f(po) * tanh_f(cn);
            creg[q] = cn;
            hnv[q] = hn;
        }

        // ---- write hnext (tf32-rounded, permuted)
        #pragma unroll
        for (int q = 0; q < 4; q++) {
            size_t f4 = ((size_t)bIdx * 4 + q) * 32 + lane_h;
            hnext[f4 * 4 + v_h] = tf32_rnaf(hnv[q]);
        }

        // ---- barrier arrive (hierarchical; releases h stores)
        __syncthreads();
        unsigned mygen = 0;
        if (tid == 0) {
            volatile unsigned* genp = &g_bar_gen;
            mygen = *genp;
            bar_arrive(bIdx);
        }

        // ---- hidden work between arrive and wait: ys stores + next prefetch
        #pragma unroll
        for (int q = 0; q < 4; q++)
            out[2 * B_ * H_ + ((size_t)bq[q] * T_ + t) * H_ + j] = hnv[q];
        if (t == T_ - 1) {
            #pragma unroll
            for (int q = 0; q < 4; q++)
                out[B_ * H_ + (size_t)bq[q] * H_ + j] = hnv[q];
        }
        if (t + 1 < T_) prefetch_xp(t + 1);

        // ---- barrier wait
        if (tid == 0) {
            volatile unsigned* genp = &g_bar_gen;
            while (*genp == mygen) { }
            __threadfence();                    // acquire
        }
        __syncthreads();
    }

    // cT
    #pragma unroll
    for (int q = 0; q < 4; q++)
        out[(size_t)bq[q] * H_ + j] = creg[q];
}

// ============================================================================
// Launch. Inputs: c0, h0, xs, Wx, Wh, b. Output fp32: [cT][hT][ys]
// ============================================================================
extern "C" void kernel_launch(void* const* d_in, const int* in_sizes, int n_in,
                              void* d_out, int out_size) {
    const float* c0   = (const float*)d_in[0];
    const float* h0   = (const float*)d_in[1];
    const float* xs   = (const float*)d_in[2];
    const float* Wx   = (const float*)d_in[3];
    const float* Wh   = (const float*)d_in[4];
    const float* bias = (const float*)d_in[5];
    float* out = (float*)d_out;

    constexpr int G_SMEM    = 3 * 4096 * 16;                 // 196,608 B
    constexpr int SCAN_SMEM = (32768 + 16384 + 8704) * 4;    // 231,424 B
    cudaFuncSetAttribute(xproj_kernel,
                         cudaFuncAttributeMaxDynamicSharedMemorySize, G_SMEM);
    cudaFuncSetAttribute(lstm_scan_kernel,
                         cudaFuncAttributeMaxDynamicSharedMemorySize, SCAN_SMEM);

    permA_kernel<<<32768, 256>>>(xs);     // 2048*128*32 f4 / 256
    permB_kernel<<<4096, 256>>>(Wx);      // 128*128*2*32 f4 / 256
    dim3 gridG(32, 256);                  // n-tiles fastest (L2-friendly)
    xproj_kernel<<<gridG, 256, G_SMEM>>>();
    lstm_scan_kernel<<<128, 128, SCAN_SMEM>>>(c0, h0, Wh, bias, out);
}